// round 3
// baseline (speedup 1.0000x reference)
#include <cuda_runtime.h>
#include <cuda.h>
#include <cstdint>

#define BB 8
#define SS 1024
#define HH 128

// ---------------- scratch ----------------
__device__ float g_scores[(size_t)BB * SS * SS];        // holds e = exp(score)
__device__ float g_part[(size_t)BB * SS * 32];          // per-jblock partial row sums
__device__ float g_denom[(size_t)BB * SS];              // row denominators

// ---------------- helpers ----------------
__device__ __forceinline__ void ffma2(unsigned long long &acc, unsigned long long a, unsigned long long b) {
    asm("fma.rn.f32x2 %0, %1, %2, %0;" : "+l"(acc) : "l"(a), "l"(b));
}
__device__ __forceinline__ void unpack2(unsigned long long p, float &lo, float &hi) {
    asm("mov.b64 {%0, %1}, %2;" : "=f"(lo), "=f"(hi) : "l"(p));
}
__device__ __forceinline__ void cpa16(uint32_t s, const void* g) {
    asm volatile("cp.async.cg.shared.global [%0], [%1], 16;" :: "r"(s), "l"(g));
}
#define CP_COMMIT() asm volatile("cp.async.commit_group;" ::: "memory")
#define CP_WAIT1()  asm volatile("cp.async.wait_group 1;" ::: "memory")

#define MBARRIER_INIT(a, n) \
    asm volatile("mbarrier.init.shared.b64 [%0], %1;" :: "r"(a), "r"(n) : "memory")
#define MBARRIER_EXPECT_TX(a, tx) \
    asm volatile("mbarrier.arrive.expect_tx.shared.b64 _, [%0], %1;" :: "r"(a), "r"(tx) : "memory")
#define MBARRIER_ARRIVE(a) \
    asm volatile("mbarrier.arrive.release.cta.shared.b64 _, [%0];" :: "r"(a) : "memory")
#define MBARRIER_WAIT(a, ph) do { \
    asm volatile("{\n\t.reg .pred P;\n\tWL%=:\n\t" \
        "mbarrier.try_wait.parity.acquire.cta.shared::cta.b64 P, [%0], %1, 0x989680;\n\t" \
        "@P bra.uni WD%=;\n\tbra.uni WL%=;\n\tWD%=:\n\t}" \
        :: "r"(a), "r"(ph) : "memory"); \
} while (0)
#define TMA_LOAD_3D(smem_addr, map, cx, cy, cz, mbar) \
    asm volatile("cp.async.bulk.tensor.3d.shared::cta.global.tile.mbarrier::complete_tx::bytes " \
        "[%0], [%1, {%2, %3, %4}], [%5];" \
        :: "r"((uint32_t)(smem_addr)), "l"(map), "r"((int)(cx)), "r"((int)(cy)), "r"((int)(cz)), \
           "r"((uint32_t)(mbar)) : "memory")

// =====================================================================
// Kernel A: e[b,i,j] = exp(sum_h x[b,j,h]*rel[i,j,h]); also per-jblock row sums.
// 256 thr = 32 j lanes x 4 i-groups(8i) x 2 b-groups(4b).
// TMA 5-stage pipeline (rel 32KB + x 8KB per stage, HCA=8, SWIZZLE_32B).
// =====================================================================
#define TIA 32
#define TJA 32
#define HCA 8
#define NCHA (HH / HCA)         // 16
#define NSTAGE 5
#define REL_BYTES (TIA * TJA * HCA * 4)   // 32768
#define X_BYTES   (BB * TJA * HCA * 4)    // 8192
#define STAGE_BYTES (REL_BYTES + X_BYTES) // 40960
#define SMEMA (1024 + NSTAGE * STAGE_BYTES)

__global__ void __launch_bounds__(256, 1)
scores_kernel(const __grid_constant__ CUtensorMap tmr,
              const __grid_constant__ CUtensorMap tmx,
              float* __restrict__ scores,
              float* __restrict__ part) {
    extern __shared__ __align__(1024) char sm[];
    const uint32_t sbase = (uint32_t)__cvta_generic_to_shared(sm);
    const uint32_t mb = sbase;                 // barrier region [0,1024)
    const int t  = threadIdx.x;
    const int j  = t & 31;
    const int g  = t >> 5;
    const int ig = g & 3;
    const int bg = g >> 2;
    const int i0 = blockIdx.y * TIA;
    const int j0 = blockIdx.x * TJA;
    const int jx = ((j >> 2) & 1) << 4;        // SW32 read-side xor (constant/thread)

    if (t == 0) {
#pragma unroll
        for (int s = 0; s < NSTAGE; s++) {
            MBARRIER_INIT(mb + s * 16, 1);       // full
            MBARRIER_INIT(mb + s * 16 + 8, 256); // empty
        }
    }
    __syncthreads();

    // prologue: issue stages 0..4
    if (t == 0) {
#pragma unroll
        for (int n = 0; n < NSTAGE; n++) {
            uint32_t fb = mb + n * 16;
            uint32_t dst = sbase + 1024 + n * STAGE_BYTES;
            MBARRIER_EXPECT_TX(fb, STAGE_BYTES);
            TMA_LOAD_3D(dst, &tmr, n * HCA, j0, i0, fb);
            TMA_LOAD_3D(dst + REL_BYTES, &tmx, n * HCA, j0, 0, fb);
        }
    }

    unsigned long long acc[8][4] = {};

    for (int c = 0; c < NCHA; c++) {
        const int slot = c % NSTAGE;
        const int ph = (c / NSTAGE) & 1;
        MBARRIER_WAIT(mb + slot * 16, ph);

        const char* st = sm + 1024 + slot * STAGE_BYTES;
        const char* rb = st + (ig * 8) * (TJA * 32) + j * 32;
        const char* xb = st + REL_BYTES + (bg * 4) * (TJA * 32) + j * 32;
#pragma unroll
        for (int f = 0; f < 2; f++) {
            const int fo = 16 * f ^ jx;
            ulonglong2 xv[4];
#pragma unroll
            for (int q = 0; q < 4; q++)
                xv[q] = *(const ulonglong2*)(xb + q * (TJA * 32) + fo);
#pragma unroll
            for (int p = 0; p < 8; p++) {
                ulonglong2 rv = *(const ulonglong2*)(rb + p * (TJA * 32) + fo);
#pragma unroll
                for (int q = 0; q < 4; q++) {
                    ffma2(acc[p][q], rv.x, xv[q].x);
                    ffma2(acc[p][q], rv.y, xv[q].y);
                }
            }
        }
        MBARRIER_ARRIVE(mb + slot * 16 + 8);

        if (t == 0 && c + NSTAGE < NCHA) {
            const int n = c + NSTAGE;
            const int eph = ((n / NSTAGE) + 1) & 1;
            uint32_t eb = mb + slot * 16 + 8;
            MBARRIER_WAIT(eb, eph);
            uint32_t fb = mb + slot * 16;
            uint32_t dst = sbase + 1024 + slot * STAGE_BYTES;
            MBARRIER_EXPECT_TX(fb, STAGE_BYTES);
            TMA_LOAD_3D(dst, &tmr, n * HCA, j0, i0, fb);
            TMA_LOAD_3D(dst + REL_BYTES, &tmx, n * HCA, j0, 0, fb);
        }
    }

    // epilogue: exp (no max-subtract: |score| <= ~70, safe in f32),
    // store e, warp-reduce row partials over the 32 j lanes.
#pragma unroll
    for (int p = 0; p < 8; p++)
#pragma unroll
        for (int q = 0; q < 4; q++) {
            float lo, hi; unpack2(acc[p][q], lo, hi);
            float e = __expf(lo + hi);
            const int i = i0 + ig * 8 + p;
            const int b = bg * 4 + q;
            scores[((size_t)b * SS + i) * SS + j0 + j] = e;
            float s = e;
#pragma unroll
            for (int o = 16; o > 0; o >>= 1) s += __shfl_xor_sync(0xffffffffu, s, o);
            if (j == 0)
                part[(((size_t)b * SS + i) << 5) + blockIdx.x] = s;
        }
}

// ---------------- reduce: denom[r] = sum of 32 partials ----------------
__global__ void reduce_kernel(const float* __restrict__ part, float* __restrict__ denom) {
    const int r = blockIdx.x * 256 + threadIdx.x;   // 8192 rows
    const float* p = part + ((size_t)r << 5);
    float s = 0.f;
#pragma unroll
    for (int k = 0; k < 32; k++) s += p[k];
    denom[r] = s;
}

// =====================================================================
// Kernel B: out[b,i,h] = (sum_j e[b,i,j]*x[b,j,h]) / denom[b,i]
// =====================================================================
#define MTB 32
#define KTB 32
#define NCHB (SS / KTB)
#define WROW 36
#define XROW 132
#define WF (MTB * WROW)
#define XFB (KTB * XROW)
#define BUFBF (WF + XFB)
#define NBUFB 3

__global__ void __launch_bounds__(128, 1)
out_kernel(const float* __restrict__ w,
           const float* __restrict__ x,
           const float* __restrict__ denom,
           float* __restrict__ out) {
    extern __shared__ float smB[];
    const int t  = threadIdx.x;
    const int tx = t & 31;
    const int ty = t >> 5;
    const int b  = blockIdx.y;
    const int m0 = blockIdx.x * MTB;
    const float* wb = w + (size_t)b * SS * SS;
    const float* xb = x + (size_t)b * SS * HH;
    const uint32_t sbase = (uint32_t)__cvta_generic_to_shared(smB);

    auto stage = [&](int c, int s) {
        uint32_t bbase = sbase + (uint32_t)s * (BUFBF * 4);
#pragma unroll
        for (int k = 0; k < 2; k++) {
            int idx = t + k * 128;
            int f4 = idx & 7, row = idx >> 3;
            cpa16(bbase + (uint32_t)(row * WROW + f4 * 4) * 4,
                  wb + (size_t)(m0 + row) * SS + c * KTB + f4 * 4);
        }
#pragma unroll
        for (int k = 0; k < 8; k++) {
            int idx = t + k * 128;
            int f4 = idx & 31, row = idx >> 5;
            cpa16(bbase + (uint32_t)(WF + row * XROW + f4 * 4) * 4,
                  xb + (size_t)(c * KTB + row) * HH + f4 * 4);
        }
    };

    stage(0, 0); CP_COMMIT();
    stage(1, 1); CP_COMMIT();

    unsigned long long acc[8][2] = {};

    int buf = 0;
    for (int c = 0; c < NCHB; c++) {
        CP_WAIT1();
        __syncthreads();
        if (c + 2 < NCHB) {
            int nb = buf + 2; if (nb >= NBUFB) nb -= NBUFB;
            stage(c + 2, nb);
        }
        CP_COMMIT();

        const float* wsb = smB + (size_t)buf * BUFBF;
        const float* xsb = wsb + WF;
#pragma unroll
        for (int j4 = 0; j4 < KTB / 4; j4++) {
            float4 wv[8];
#pragma unroll
            for (int p = 0; p < 8; p++)
                wv[p] = *reinterpret_cast<const float4*>(wsb + (ty * 8 + p) * WROW + j4 * 4);
#pragma unroll
            for (int jj = 0; jj < 4; jj++) {
                ulonglong2 xv = *reinterpret_cast<const ulonglong2*>(xsb + (j4 * 4 + jj) * XROW + tx * 4);
#pragma unroll
                for (int p = 0; p < 8; p++) {
                    float wval = (jj == 0) ? wv[p].x : (jj == 1) ? wv[p].y : (jj == 2) ? wv[p].z : wv[p].w;
                    unsigned long long wp;
                    asm("mov.b64 %0, {%1, %1};" : "=l"(wp) : "f"(wval));
                    ffma2(acc[p][0], wp, xv.x);
                    ffma2(acc[p][1], wp, xv.y);
                }
            }
        }
        buf++; if (buf == NBUFB) buf = 0;
    }

#pragma unroll
    for (int p = 0; p < 8; p++) {
        float inv = 1.0f / denom[(size_t)b * SS + m0 + ty * 8 + p];
        float4 o;
        unpack2(acc[p][0], o.x, o.y);
        unpack2(acc[p][1], o.z, o.w);
        o.x *= inv; o.y *= inv; o.z *= inv; o.w *= inv;
        *reinterpret_cast<float4*>(out + ((size_t)b * SS + m0 + ty * 8 + p) * HH + tx * 4) = o;
    }
}

// ---------------- launch ----------------
typedef CUresult (*EncodeFn)(CUtensorMap*, CUtensorMapDataType, cuuint32_t, void*,
                             const cuuint64_t*, const cuuint64_t*, const cuuint32_t*,
                             const cuuint32_t*, CUtensorMapInterleave, CUtensorMapSwizzle,
                             CUtensorMapL2promotion, CUtensorMapFloatOOBfill);

extern "C" void kernel_launch(void* const* d_in, const int* in_sizes, int n_in,
                              void* d_out, int out_size) {
    const float* x   = (const float*)d_in[0];   // (8, 1024, 128) f32
    const float* rel = (const float*)d_in[1];   // (1024, 1024, 128) f32
    float* out = (float*)d_out;

    float *scores = nullptr, *part = nullptr, *denom = nullptr;
    cudaGetSymbolAddress((void**)&scores, g_scores);
    cudaGetSymbolAddress((void**)&part, g_part);
    cudaGetSymbolAddress((void**)&denom, g_denom);

    // tensor maps (driver entry point via runtime; no allocations)
    EncodeFn enc = nullptr;
    cudaDriverEntryPointQueryResult qr;
    cudaGetDriverEntryPoint("cuTensorMapEncodeTiled", (void**)&enc, cudaEnableDefault, &qr);

    CUtensorMap tmr, tmx;
    {
        cuuint64_t dims[3]    = {HH, SS, SS};
        cuuint64_t strides[2] = {HH * 4ull, (cuuint64_t)SS * HH * 4ull};
        cuuint32_t box[3]     = {HCA, TJA, TIA};
        cuuint32_t es[3]      = {1, 1, 1};
        enc(&tmr, CU_TENSOR_MAP_DATA_TYPE_FLOAT32, 3, (void*)rel, dims, strides, box, es,
            CU_TENSOR_MAP_INTERLEAVE_NONE, CU_TENSOR_MAP_SWIZZLE_32B,
            CU_TENSOR_MAP_L2_PROMOTION_L2_128B, CU_TENSOR_MAP_FLOAT_OOB_FILL_NONE);
    }
    {
        cuuint64_t dims[3]    = {HH, SS, BB};
        cuuint64_t strides[2] = {HH * 4ull, (cuuint64_t)SS * HH * 4ull};
        cuuint32_t box[3]     = {HCA, TJA, BB};
        cuuint32_t es[3]      = {1, 1, 1};
        enc(&tmx, CU_TENSOR_MAP_DATA_TYPE_FLOAT32, 3, (void*)x, dims, strides, box, es,
            CU_TENSOR_MAP_INTERLEAVE_NONE, CU_TENSOR_MAP_SWIZZLE_32B,
            CU_TENSOR_MAP_L2_PROMOTION_L2_128B, CU_TENSOR_MAP_FLOAT_OOB_FILL_NONE);
    }

    cudaFuncSetAttribute(scores_kernel, cudaFuncAttributeMaxDynamicSharedMemorySize, SMEMA);
    scores_kernel<<<dim3(SS / TJA, SS / TIA), 256, SMEMA>>>(tmr, tmx, scores, part);

    reduce_kernel<<<BB * SS / 256, 256>>>(part, denom);

    const int smB_bytes = NBUFB * BUFBF * 4;
    cudaFuncSetAttribute(out_kernel, cudaFuncAttributeMaxDynamicSharedMemorySize, smB_bytes);
    out_kernel<<<dim3(SS / MTB, BB), 128, smB_bytes>>>(scores, x, denom, out);
}

// round 4
// speedup vs baseline: 1.5183x; 1.5183x over previous
#include <cuda_runtime.h>
#include <cuda.h>
#include <cstdint>

#define BB 8
#define SS 1024
#define HH 128

// ---------------- scratch ----------------
__device__ float g_scores[(size_t)BB * SS * SS];        // e = exp(score)
__device__ float g_part[(size_t)BB * SS * 32];          // per-jblock partial row sums
__device__ float g_denom[(size_t)BB * SS];              // row denominators

// ---------------- helpers ----------------
__device__ __forceinline__ void ffma2(unsigned long long &acc, unsigned long long a, unsigned long long b) {
    asm("fma.rn.f32x2 %0, %1, %2, %0;" : "+l"(acc) : "l"(a), "l"(b));
}
__device__ __forceinline__ void unpack2(unsigned long long p, float &lo, float &hi) {
    asm("mov.b64 {%0, %1}, %2;" : "=f"(lo), "=f"(hi) : "l"(p));
}
__device__ __forceinline__ void cpa16(uint32_t s, const void* g) {
    asm volatile("cp.async.cg.shared.global [%0], [%1], 16;" :: "r"(s), "l"(g));
}
#define CP_COMMIT() asm volatile("cp.async.commit_group;" ::: "memory")
#define CP_WAIT1()  asm volatile("cp.async.wait_group 1;" ::: "memory")

#define MBARRIER_INIT(a, n) \
    asm volatile("mbarrier.init.shared.b64 [%0], %1;" :: "r"(a), "r"(n) : "memory")
#define MBARRIER_EXPECT_TX(a, tx) \
    asm volatile("mbarrier.arrive.expect_tx.shared.b64 _, [%0], %1;" :: "r"(a), "r"(tx) : "memory")
#define MBARRIER_ARRIVE(a) \
    asm volatile("mbarrier.arrive.release.cta.shared.b64 _, [%0];" :: "r"(a) : "memory")
#define MBARRIER_WAIT(a, ph) do { \
    asm volatile("{\n\t.reg .pred P;\n\tWL%=:\n\t" \
        "mbarrier.try_wait.parity.acquire.cta.shared::cta.b64 P, [%0], %1, 0x989680;\n\t" \
        "@P bra.uni WD%=;\n\tbra.uni WL%=;\n\tWD%=:\n\t}" \
        :: "r"(a), "r"(ph) : "memory"); \
} while (0)
#define TMA_LOAD_3D(smem_addr, map, cx, cy, cz, mbar) \
    asm volatile("cp.async.bulk.tensor.3d.shared::cta.global.tile.mbarrier::complete_tx::bytes " \
        "[%0], [%1, {%2, %3, %4}], [%5];" \
        :: "r"((uint32_t)(smem_addr)), "l"(map), "r"((int)(cx)), "r"((int)(cy)), "r"((int)(cz)), \
           "r"((uint32_t)(mbar)) : "memory")

// =====================================================================
// Kernel A: e[b,i,j] = exp(sum_h x[b,j,h]*rel[i,j,h]) + per-jblock row sums.
// 256 thr = 32 j lanes x 4 i-groups(8i) x 2 h-halves. Thread tile 8i x 8b x 4h.
// rel smem read exactly once; x read 4x. TMA 5-stage, rotating producer warp.
// =====================================================================
#define TIA 32
#define TJA 32
#define HCA 8
#define NCHA (HH / HCA)         // 16
#define NSTAGE 5
#define REL_BYTES (TIA * TJA * HCA * 4)   // 32768
#define X_BYTES   (BB * TJA * HCA * 4)    // 8192
#define STAGE_BYTES (REL_BYTES + X_BYTES) // 40960
#define SMEMA (1024 + NSTAGE * STAGE_BYTES)

__global__ void __launch_bounds__(256, 1)
scores_kernel(const __grid_constant__ CUtensorMap tmr,
              const __grid_constant__ CUtensorMap tmx,
              float* __restrict__ scores,
              float* __restrict__ part) {
    extern __shared__ __align__(1024) char sm[];
    const uint32_t sbase = (uint32_t)__cvta_generic_to_shared(sm);
    const uint32_t mb = sbase;
    const int t  = threadIdx.x;
    const int j  = t & 31;
    const int g  = t >> 5;
    const int hg = g >> 2;       // h-half (warps 0-3: hg=0 across all SMSPs)
    const int ig = g & 3;        // i-group: rows ig*8..+7
    const int i0 = blockIdx.y * TIA;
    const int j0 = blockIdx.x * TJA;
    const int fo = (16 * hg) ^ (((j >> 2) & 1) << 4);  // SW32 xor, constant/thread

    if (t == 0) {
#pragma unroll
        for (int s = 0; s < NSTAGE; s++) {
            MBARRIER_INIT(mb + s * 16, 1);       // full
            MBARRIER_INIT(mb + s * 16 + 8, 256); // empty
        }
    }
    __syncthreads();

    if (t == 0) {
#pragma unroll
        for (int n = 0; n < NSTAGE; n++) {
            uint32_t fb = mb + n * 16;
            uint32_t dst = sbase + 1024 + n * STAGE_BYTES;
            MBARRIER_EXPECT_TX(fb, STAGE_BYTES);
            TMA_LOAD_3D(dst, &tmr, n * HCA, j0, i0, fb);
            TMA_LOAD_3D(dst + REL_BYTES, &tmx, n * HCA, j0, 0, fb);
        }
    }

    unsigned long long acc[8][8] = {};   // 8 i x 8 b, one f32x2 each (half-h)

    for (int c = 0; c < NCHA; c++) {
        const int slot = c % NSTAGE;
        const int ph = (c / NSTAGE) & 1;
        MBARRIER_WAIT(mb + slot * 16, ph);

        const char* st = sm + 1024 + slot * STAGE_BYTES;
        const char* rb = st + ((ig * 8) * TJA + j) * 32 + fo;
        const char* xb = st + REL_BYTES + (size_t)j * 32 + fo;

        ulonglong2 xv[8], rv[8];
#pragma unroll
        for (int q = 0; q < 8; q++)
            xv[q] = *(const ulonglong2*)(xb + q * (TJA * 32));
#pragma unroll
        for (int p = 0; p < 8; p++)
            rv[p] = *(const ulonglong2*)(rb + p * (TJA * 32));

        MBARRIER_ARRIVE(mb + slot * 16 + 8);

        // rotating producer: warp (c&7) issues chunk c+NSTAGE
        if (g == (c & 7) && c + NSTAGE < NCHA) {
            const int n = c + NSTAGE;
            const int eph = ((n / NSTAGE) + 1) & 1;
            MBARRIER_WAIT(mb + slot * 16 + 8, eph);
            if (j == 0) {
                uint32_t fb = mb + slot * 16;
                uint32_t dst = sbase + 1024 + slot * STAGE_BYTES;
                MBARRIER_EXPECT_TX(fb, STAGE_BYTES);
                TMA_LOAD_3D(dst, &tmr, n * HCA, j0, i0, fb);
                TMA_LOAD_3D(dst + REL_BYTES, &tmx, n * HCA, j0, 0, fb);
            }
        }

#pragma unroll
        for (int p = 0; p < 8; p++)
#pragma unroll
            for (int q = 0; q < 8; q++) {
                ffma2(acc[p][q], rv[p].x, xv[q].x);
                ffma2(acc[p][q], rv[p].y, xv[q].y);
            }
    }

    // combine h-halves via smem, then exp + store + row partial sums
    __syncthreads();
    float* red = (float*)(sm + 1024);   // 32KB scratch (pipeline done)
    if (hg == 1) {
#pragma unroll
        for (int p = 0; p < 8; p++)
#pragma unroll
            for (int q = 0; q < 8; q++) {
                float lo, hi; unpack2(acc[p][q], lo, hi);
                red[(((ig * 8 + p) * 8) + q) * 32 + j] = lo + hi;
            }
    }
    __syncthreads();
    if (hg == 0) {
#pragma unroll
        for (int p = 0; p < 8; p++) {
            const int i = i0 + ig * 8 + p;
#pragma unroll
            for (int q = 0; q < 8; q++) {
                float lo, hi; unpack2(acc[p][q], lo, hi);
                float v = lo + hi + red[(((ig * 8 + p) * 8) + q) * 32 + j];
                float e = __expf(v);   // no max-subtract: |score| small, f32-safe
                scores[((size_t)q * SS + i) * SS + j0 + j] = e;
                float s = e;
#pragma unroll
                for (int o = 16; o > 0; o >>= 1) s += __shfl_xor_sync(0xffffffffu, s, o);
                if (j == 0)
                    part[(((size_t)q * SS + i) << 5) + blockIdx.x] = s;
            }
        }
    }
}

// ---------------- reduce: denom[r] = sum of 32 partials ----------------
__global__ void reduce_kernel(const float* __restrict__ part, float* __restrict__ denom) {
    const int r = blockIdx.x * 256 + threadIdx.x;
    const float* p = part + ((size_t)r << 5);
    float s = 0.f;
#pragma unroll
    for (int k = 0; k < 32; k++) s += p[k];
    denom[r] = s;
}

// =====================================================================
// Kernel B: out[b,i,h] = (sum_j e[b,i,j]*x[b,j,h]) / denom[b,i]
// 256 thr, MTB=64 -> grid 16x8=128 blocks, single wave, 8 warps/SM.
// =====================================================================
#define MTB 64
#define KTB 32
#define NCHB (SS / KTB)
#define WROW 36
#define XROW 132
#define WF (MTB * WROW)      // 2304 floats
#define XFB (KTB * XROW)     // 4224 floats
#define BUFBF (WF + XFB)     // 6528 floats
#define NBUFB 3

__global__ void __launch_bounds__(256, 1)
out_kernel(const float* __restrict__ w,
           const float* __restrict__ x,
           const float* __restrict__ denom,
           float* __restrict__ out) {
    extern __shared__ float smB[];
    const int t  = threadIdx.x;
    const int tx = t & 31;       // h quad
    const int ty = t >> 5;       // 8 groups of 8 i-rows
    const int b  = blockIdx.y;
    const int m0 = blockIdx.x * MTB;
    const float* wb = w + (size_t)b * SS * SS;
    const float* xb = x + (size_t)b * SS * HH;
    const uint32_t sbase = (uint32_t)__cvta_generic_to_shared(smB);

    auto stage = [&](int c, int s) {
        uint32_t bbase = sbase + (uint32_t)s * (BUFBF * 4);
        // w: 64 rows x 8 float4 = 512 f4
#pragma unroll
        for (int k = 0; k < 2; k++) {
            int idx = t + k * 256;
            int f4 = idx & 7, row = idx >> 3;
            cpa16(bbase + (uint32_t)(row * WROW + f4 * 4) * 4,
                  wb + (size_t)(m0 + row) * SS + c * KTB + f4 * 4);
        }
        // x: 32 rows x 32 float4 = 1024 f4
#pragma unroll
        for (int k = 0; k < 4; k++) {
            int idx = t + k * 256;
            int f4 = idx & 31, row = idx >> 5;
            cpa16(bbase + (uint32_t)(WF + row * XROW + f4 * 4) * 4,
                  xb + (size_t)(c * KTB + row) * HH + f4 * 4);
        }
    };

    stage(0, 0); CP_COMMIT();
    stage(1, 1); CP_COMMIT();

    unsigned long long acc[8][2] = {};

    int buf = 0;
    for (int c = 0; c < NCHB; c++) {
        CP_WAIT1();
        __syncthreads();
        if (c + 2 < NCHB) {
            int nb = buf + 2; if (nb >= NBUFB) nb -= NBUFB;
            stage(c + 2, nb);
        }
        CP_COMMIT();

        const float* wsb = smB + (size_t)buf * BUFBF;
        const float* xsb = wsb + WF;
#pragma unroll
        for (int j4 = 0; j4 < KTB / 4; j4++) {
            float4 wv[8];
#pragma unroll
            for (int p = 0; p < 8; p++)
                wv[p] = *reinterpret_cast<const float4*>(wsb + (ty * 8 + p) * WROW + j4 * 4);
#pragma unroll
            for (int jj = 0; jj < 4; jj++) {
                ulonglong2 xv = *reinterpret_cast<const ulonglong2*>(xsb + (j4 * 4 + jj) * XROW + tx * 4);
#pragma unroll
                for (int p = 0; p < 8; p++) {
                    float wval = (jj == 0) ? wv[p].x : (jj == 1) ? wv[p].y : (jj == 2) ? wv[p].z : wv[p].w;
                    unsigned long long wp;
                    asm("mov.b64 %0, {%1, %1};" : "=l"(wp) : "f"(wval));
                    ffma2(acc[p][0], wp, xv.x);
                    ffma2(acc[p][1], wp, xv.y);
                }
            }
        }
        buf++; if (buf == NBUFB) buf = 0;
    }

#pragma unroll
    for (int p = 0; p < 8; p++) {
        float inv = 1.0f / denom[(size_t)b * SS + m0 + ty * 8 + p];
        float4 o;
        unpack2(acc[p][0], o.x, o.y);
        unpack2(acc[p][1], o.z, o.w);
        o.x *= inv; o.y *= inv; o.z *= inv; o.w *= inv;
        *reinterpret_cast<float4*>(out + ((size_t)b * SS + m0 + ty * 8 + p) * HH + tx * 4) = o;
    }
}

// ---------------- launch ----------------
typedef CUresult (*EncodeFn)(CUtensorMap*, CUtensorMapDataType, cuuint32_t, void*,
                             const cuuint64_t*, const cuuint64_t*, const cuuint32_t*,
                             const cuuint32_t*, CUtensorMapInterleave, CUtensorMapSwizzle,
                             CUtensorMapL2promotion, CUtensorMapFloatOOBfill);

extern "C" void kernel_launch(void* const* d_in, const int* in_sizes, int n_in,
                              void* d_out, int out_size) {
    const float* x   = (const float*)d_in[0];   // (8, 1024, 128) f32
    const float* rel = (const float*)d_in[1];   // (1024, 1024, 128) f32
    float* out = (float*)d_out;

    float *scores = nullptr, *part = nullptr, *denom = nullptr;
    cudaGetSymbolAddress((void**)&scores, g_scores);
    cudaGetSymbolAddress((void**)&part, g_part);
    cudaGetSymbolAddress((void**)&denom, g_denom);

    EncodeFn enc = nullptr;
    cudaDriverEntryPointQueryResult qr;
    cudaGetDriverEntryPoint("cuTensorMapEncodeTiled", (void**)&enc, cudaEnableDefault, &qr);

    CUtensorMap tmr, tmx;
    {
        cuuint64_t dims[3]    = {HH, SS, SS};
        cuuint64_t strides[2] = {HH * 4ull, (cuuint64_t)SS * HH * 4ull};
        cuuint32_t box[3]     = {HCA, TJA, TIA};
        cuuint32_t es[3]      = {1, 1, 1};
        enc(&tmr, CU_TENSOR_MAP_DATA_TYPE_FLOAT32, 3, (void*)rel, dims, strides, box, es,
            CU_TENSOR_MAP_INTERLEAVE_NONE, CU_TENSOR_MAP_SWIZZLE_32B,
            CU_TENSOR_MAP_L2_PROMOTION_L2_128B, CU_TENSOR_MAP_FLOAT_OOB_FILL_NONE);
    }
    {
        cuuint64_t dims[3]    = {HH, SS, BB};
        cuuint64_t strides[2] = {HH * 4ull, (cuuint64_t)SS * HH * 4ull};
        cuuint32_t box[3]     = {HCA, TJA, BB};
        cuuint32_t es[3]      = {1, 1, 1};
        enc(&tmx, CU_TENSOR_MAP_DATA_TYPE_FLOAT32, 3, (void*)x, dims, strides, box, es,
            CU_TENSOR_MAP_INTERLEAVE_NONE, CU_TENSOR_MAP_SWIZZLE_32B,
            CU_TENSOR_MAP_L2_PROMOTION_L2_128B, CU_TENSOR_MAP_FLOAT_OOB_FILL_NONE);
    }

    cudaFuncSetAttribute(scores_kernel, cudaFuncAttributeMaxDynamicSharedMemorySize, SMEMA);
    scores_kernel<<<dim3(SS / TJA, SS / TIA), 256, SMEMA>>>(tmr, tmx, scores, part);

    reduce_kernel<<<BB * SS / 256, 256>>>(part, denom);

    const int smB_bytes = NBUFB * BUFBF * 4;
    cudaFuncSetAttribute(out_kernel, cudaFuncAttributeMaxDynamicSharedMemorySize, smB_bytes);
    out_kernel<<<dim3(SS / MTB, BB), 256, smB_bytes>>>(scores, x, denom, out);
}